// round 4
// baseline (speedup 1.0000x reference)
#include <cuda_runtime.h>
#include <cuda_fp16.h>

// bilateral_grid: [N=2, C=12, D=8, Hg=16, Wg=16] f32  (d_in[0])
// guidemap:       [N=2, 1, 2048, 2048] f32            (d_in[1])
// out:            [N=2, C=12, 2048, 2048] f32
//
// One block per (n, h) row. x-interp constant per row -> precompute
// Gx[y][z][c-pair] as half2 in smem. Each thread owns 8 consecutive pixels
// (2 groups of 4): guide prefetched with LDG.128, 4 independent sampling
// chains per group, stores as STG.128 per channel.

#define CG   12
#define DG   8
#define HGG  16
#define WGG  16
#define HH   2048
#define WW   2048

#define C2    6            // 6 half2 words per corner row
#define ZSTR  8            // words per (y,z) row: 6 used + 2 pad
#define YSTR  68           // 8*8=64 + 4 pad
#define SMEM_U32 (HGG * YSTR)   // 1088 words = 4.25 KB

struct Row6 { __half2 v[C2]; };

__device__ __forceinline__ Row6 load_row(const unsigned int* sg, int off)
{
    Row6 r;
    const uint4 a = *reinterpret_cast<const uint4*>(sg + off);       // LDS.128
    const uint2 b = *reinterpret_cast<const uint2*>(sg + off + 4);   // LDS.64
    r.v[0] = *reinterpret_cast<const __half2*>(&a.x);
    r.v[1] = *reinterpret_cast<const __half2*>(&a.y);
    r.v[2] = *reinterpret_cast<const __half2*>(&a.z);
    r.v[3] = *reinterpret_cast<const __half2*>(&a.w);
    r.v[4] = *reinterpret_cast<const __half2*>(&b.x);
    r.v[5] = *reinterpret_cast<const __half2*>(&b.y);
    return r;
}

// Sample one pixel into acc[12]
__device__ __forceinline__ void sample_px(const unsigned int* sg, int w, float g,
                                          float scale, float* acc)
{
    const float iy = w * scale;
    const float iz = fmaf(g, 3.5f, 3.5f);

    const float fy0f = floorf(iy), fz0f = floorf(iz);
    const float fy = iy - fy0f, fz = iz - fz0f;
    int y0 = (int)fy0f, z0 = (int)fz0f;
    y0 = max(0, min(y0, HGG - 1));
    z0 = max(0, min(z0, DG - 1));
    const int y1 = min(y0 + 1, HGG - 1);
    const int z1 = min(z0 + 1, DG - 1);

    const __half2 hy0 = __float2half2_rn(1.0f - fy);
    const __half2 hy1 = __float2half2_rn(fy);

    const Row6 A  = load_row(sg, y0 * YSTR + z0 * ZSTR);
    const Row6 B  = load_row(sg, y1 * YSTR + z0 * ZSTR);
    const Row6 Cc = load_row(sg, y0 * YSTR + z1 * ZSTR);
    const Row6 Dd = load_row(sg, y1 * YSTR + z1 * ZSTR);

    const float wz1 = fz, wz0 = 1.0f - fz;
#pragma unroll
    for (int k = 0; k < C2; k++) {
        const __half2 s0 = __hfma2(hy1, B.v[k],  __hmul2(hy0, A.v[k]));
        const __half2 s1 = __hfma2(hy1, Dd.v[k], __hmul2(hy0, Cc.v[k]));
        const float2 a = __half22float2(s0);
        const float2 b = __half22float2(s1);
        acc[2 * k]     = fmaf(wz0, a.x, wz1 * b.x);
        acc[2 * k + 1] = fmaf(wz0, a.y, wz1 * b.y);
    }
}

__global__ __launch_bounds__(256, 2)
void slice_kernel(const float* __restrict__ grid,
                  const float* __restrict__ guide,
                  float* __restrict__ out)
{
    __shared__ unsigned int sg[SMEM_U32];

    const int h = blockIdx.x;
    const int n = blockIdx.y;

    const float scale = 15.0f / 2047.0f;
    const float ix   = h * scale;
    const float fx0f = floorf(ix);
    const float fx   = ix - fx0f;
    int x0 = (int)fx0f;
    x0 = max(0, min(x0, WGG - 1));
    const int x1 = min(x0 + 1, WGG - 1);
    const float wx1 = fx, wx0 = 1.0f - fx;

    // ---- stage Gx as half2 channel pairs: sg[y*YSTR + z*ZSTR + c2] ----
    const float* gsrc = grid + (size_t)n * (CG * DG * HGG * WGG);
    for (int i = threadIdx.x; i < DG * HGG * C2; i += blockDim.x) {
        const int c2 = i % C2;
        const int t  = i / C2;
        const int y  = t % HGG;
        const int z  = t / HGG;
        const int c0 = 2 * c2, c1 = c0 + 1;
        const int b0 = ((c0 * DG + z) * HGG + y) * WGG;
        const int b1 = ((c1 * DG + z) * HGG + y) * WGG;
        const float v0 = wx0 * gsrc[b0 + x0] + wx1 * gsrc[b0 + x1];
        const float v1 = wx0 * gsrc[b1 + x0] + wx1 * gsrc[b1 + x1];
        const __half2 p = __floats2half2_rn(v0, v1);
        sg[y * YSTR + z * ZSTR + c2] = *reinterpret_cast<const unsigned int*>(&p);
    }

    const int HW = HH * WW;
    const float* gd   = guide + (size_t)n * HW + (size_t)h * WW;
    float*       outn = out   + (size_t)n * (CG * HW) + (size_t)h * WW;

    // Prefetch all 8 guide values for this thread BEFORE the barrier:
    // two LDG.128 in flight while smem staging drains.
    const int w0 = threadIdx.x * 4;            // group 0 base
    const int w1 = 1024 + threadIdx.x * 4;     // group 1 base
    const float4 gv0 = *reinterpret_cast<const float4*>(gd + w0);
    const float4 gv1 = *reinterpret_cast<const float4*>(gd + w1);

    __syncthreads();

    // ---- group 0: pixels w0..w0+3 ----
    {
        float acc[4][CG];
        sample_px(sg, w0 + 0, gv0.x, scale, acc[0]);
        sample_px(sg, w0 + 1, gv0.y, scale, acc[1]);
        sample_px(sg, w0 + 2, gv0.z, scale, acc[2]);
        sample_px(sg, w0 + 3, gv0.w, scale, acc[3]);
#pragma unroll
        for (int c = 0; c < CG; c++) {
            float4 o = make_float4(acc[0][c], acc[1][c], acc[2][c], acc[3][c]);
            *reinterpret_cast<float4*>(outn + (size_t)c * HW + w0) = o;
        }
    }
    // ---- group 1: pixels w1..w1+3 ----
    {
        float acc[4][CG];
        sample_px(sg, w1 + 0, gv1.x, scale, acc[0]);
        sample_px(sg, w1 + 1, gv1.y, scale, acc[1]);
        sample_px(sg, w1 + 2, gv1.z, scale, acc[2]);
        sample_px(sg, w1 + 3, gv1.w, scale, acc[3]);
#pragma unroll
        for (int c = 0; c < CG; c++) {
            float4 o = make_float4(acc[0][c], acc[1][c], acc[2][c], acc[3][c]);
            *reinterpret_cast<float4*>(outn + (size_t)c * HW + w1) = o;
        }
    }
}

extern "C" void kernel_launch(void* const* d_in, const int* in_sizes, int n_in,
                              void* d_out, int out_size)
{
    const float* grid  = (const float*)d_in[0];
    const float* guide = (const float*)d_in[1];
    float*       out   = (float*)d_out;

    dim3 gdim(HH, 2);            // one block per (row, batch)
    slice_kernel<<<gdim, 256>>>(grid, guide, out);
}

// round 5
// speedup vs baseline: 1.1275x; 1.1275x over previous
#include <cuda_runtime.h>
#include <cuda_fp16.h>

// bilateral_grid: [N=2, C=12, D=8, Hg=16, Wg=16] f32  (d_in[0])
// guidemap:       [N=2, 1, 2048, 2048] f32            (d_in[1])
// out:            [N=2, C=12, 2048, 2048] f32
//
// One block per (n, h) row. x-interp constant per row -> Gx[y][z][c-pair] as
// half2 in smem. Each thread: 2 consecutive pixels x 4 iterations (512-px
// stride). Guide prefetched (4x LDG.64) before the staging barrier. Per pixel:
// 4 corner rows, single fused 4-corner weighted sum in half2, 12 F2F, STG.64.

#define CG   12
#define DG   8
#define HGG  16
#define WGG  16
#define HH   2048
#define WW   2048

#define C2    6             // 6 half2 words per corner row
#define ZSTR  12            // 12z mod 32 distinct for z=0..7 (no z aliasing)
#define YSTR  100           // 8*12=96 + 4 pad
#define SMEM_U32 (HGG * YSTR)

#define SCALE (15.0f / 2047.0f)

struct Row6 { __half2 v[C2]; };

__device__ __forceinline__ Row6 load_row(const unsigned int* sg, int off)
{
    Row6 r;
    const uint4 a = *reinterpret_cast<const uint4*>(sg + off);       // LDS.128
    const uint2 b = *reinterpret_cast<const uint2*>(sg + off + 4);   // LDS.64
    r.v[0] = *reinterpret_cast<const __half2*>(&a.x);
    r.v[1] = *reinterpret_cast<const __half2*>(&a.y);
    r.v[2] = *reinterpret_cast<const __half2*>(&a.z);
    r.v[3] = *reinterpret_cast<const __half2*>(&a.w);
    r.v[4] = *reinterpret_cast<const __half2*>(&b.x);
    r.v[5] = *reinterpret_cast<const __half2*>(&b.y);
    return r;
}

// Fused y/z interp for one pixel -> 6 half2 channel pairs.
__device__ __forceinline__ void sample_half(const unsigned int* sg, int w, float g,
                                            __half2* s)
{
    const float iy = w * SCALE;
    const float iz = fmaf(g, 3.5f, 3.5f);

    const float fy0f = floorf(iy), fz0f = floorf(iz);
    const float fy = iy - fy0f, fz = iz - fz0f;
    int y0 = (int)fy0f, z0 = (int)fz0f;
    y0 = max(0, min(y0, HGG - 1));
    z0 = max(0, min(z0, DG - 1));
    const int y1 = min(y0 + 1, HGG - 1);
    const int z1 = min(z0 + 1, DG - 1);

    const float wy1 = fy, wy0 = 1.0f - fy;
    const float wz1 = fz, wz0 = 1.0f - fz;

    const __half2 w00 = __float2half2_rn(wy0 * wz0);
    const __half2 w01 = __float2half2_rn(wy1 * wz0);
    const __half2 w10 = __float2half2_rn(wy0 * wz1);
    const __half2 w11 = __float2half2_rn(wy1 * wz1);

    const Row6 A = load_row(sg, y0 * YSTR + z0 * ZSTR);
    const Row6 B = load_row(sg, y1 * YSTR + z0 * ZSTR);
    const Row6 Cc = load_row(sg, y0 * YSTR + z1 * ZSTR);
    const Row6 Dd = load_row(sg, y1 * YSTR + z1 * ZSTR);

#pragma unroll
    for (int k = 0; k < C2; k++) {
        __half2 acc = __hmul2(w00, A.v[k]);
        acc = __hfma2(w01, B.v[k],  acc);
        acc = __hfma2(w10, Cc.v[k], acc);
        acc = __hfma2(w11, Dd.v[k], acc);
        s[k] = acc;
    }
}

__global__ __launch_bounds__(256, 4)
void slice_kernel(const float* __restrict__ grid,
                  const float* __restrict__ guide,
                  float* __restrict__ out)
{
    __shared__ unsigned int sg[SMEM_U32];

    const int h = blockIdx.x;
    const int n = blockIdx.y;

    const float ix   = h * SCALE;
    const float fx0f = floorf(ix);
    const float fx   = ix - fx0f;
    int x0 = (int)fx0f;
    x0 = max(0, min(x0, WGG - 1));
    const int x1 = min(x0 + 1, WGG - 1);
    const float wx1 = fx, wx0 = 1.0f - fx;

    const int HW = HH * WW;
    const float* gd   = guide + (size_t)n * HW + (size_t)h * WW;
    float*       outn = out   + (size_t)n * (CG * HW) + (size_t)h * WW;

    // Prefetch all 4 guide pairs for this thread (overlaps with staging).
    float2 gv[4];
#pragma unroll
    for (int it = 0; it < 4; it++)
        gv[it] = *reinterpret_cast<const float2*>(gd + it * 512 + threadIdx.x * 2);

    // ---- stage Gx as half2 channel pairs: sg[y*YSTR + z*ZSTR + c2] ----
    const float* gsrc = grid + (size_t)n * (CG * DG * HGG * WGG);
    for (int i = threadIdx.x; i < DG * HGG * C2; i += blockDim.x) {
        const int c2 = i % C2;
        const int t  = i / C2;
        const int y  = t % HGG;
        const int z  = t / HGG;
        const int c0 = 2 * c2, c1 = c0 + 1;
        const int b0 = ((c0 * DG + z) * HGG + y) * WGG;
        const int b1 = ((c1 * DG + z) * HGG + y) * WGG;
        const float v0 = wx0 * gsrc[b0 + x0] + wx1 * gsrc[b0 + x1];
        const float v1 = wx0 * gsrc[b1 + x0] + wx1 * gsrc[b1 + x1];
        const __half2 p = __floats2half2_rn(v0, v1);
        sg[y * YSTR + z * ZSTR + c2] = *reinterpret_cast<const unsigned int*>(&p);
    }
    __syncthreads();

#pragma unroll
    for (int it = 0; it < 4; it++) {
        const int w0 = it * 512 + threadIdx.x * 2;

        __half2 s[C2], t[C2];
        sample_half(sg, w0,     gv[it].x, s);
        sample_half(sg, w0 + 1, gv[it].y, t);

#pragma unroll
        for (int k = 0; k < C2; k++) {
            const float2 a = __half22float2(s[k]);
            const float2 b = __half22float2(t[k]);
            float2 o0 = make_float2(a.x, b.x);   // channel 2k   : px0, px1
            float2 o1 = make_float2(a.y, b.y);   // channel 2k+1 : px0, px1
            *reinterpret_cast<float2*>(outn + (size_t)(2 * k)     * HW + w0) = o0;
            *reinterpret_cast<float2*>(outn + (size_t)(2 * k + 1) * HW + w0) = o1;
        }
    }
}

extern "C" void kernel_launch(void* const* d_in, const int* in_sizes, int n_in,
                              void* d_out, int out_size)
{
    const float* grid  = (const float*)d_in[0];
    const float* guide = (const float*)d_in[1];
    float*       out   = (float*)d_out;

    dim3 gdim(HH, 2);            // one block per (row, batch)
    slice_kernel<<<gdim, 256>>>(grid, guide, out);
}